// round 1
// baseline (speedup 1.0000x reference)
#include <cuda_runtime.h>
#include <cuda_bf16.h>
#include <math.h>

// Problem constants
#define B_DIM 16
#define S_DIM 4096
#define F_DIM 512
#define NCLS 10
#define HID 64
#define ODIM 128

#define COLS_PER_CTA 4
#define NTHREADS 512
#define TAB_SLOTS 8192          // per-column hash slots (4096 values -> load factor 0.5)
#define EMPTY_SLOT 0xFFFFFFFFu  // NaN bit pattern; values are NaN->0 canonicalized, never this

// Shared memory layout (dynamic):
// phase 1: [0, 131072)              : 4 hash tables of 8192 uint32
//          [131072, 147456)         : y labels for this batch (4096 int)
// phase 2 (overlaps tables, after __syncthreads):
//          [0, 34816)               : reduction buffer 512 x 17 floats (padded stride)
//          [34816, 34912)           : stats6 (4 cols x 6)
//          [35072, 36096)           : h buffer (4 cols x 64)
//          [36864, 69632)           : w2 staged (64x128 floats)
#define OFF_TABLES   0
#define OFF_YBUF     131072
#define OFF_BUF      0
#define OFF_STATS    34816
#define OFF_H        35072
#define OFF_W2       36864
#define SMEM_BYTES   147456

__device__ float g_class_counts[B_DIM * NCLS];

__global__ void class_count_kernel(const int* __restrict__ y) {
    __shared__ int hist[NCLS];
    int b = blockIdx.x;
    if (threadIdx.x < NCLS) hist[threadIdx.x] = 0;
    __syncthreads();
    for (int i = threadIdx.x; i < S_DIM; i += blockDim.x) {
        atomicAdd(&hist[y[b * S_DIM + i]], 1);
    }
    __syncthreads();
    if (threadIdx.x < NCLS) g_class_counts[b * NCLS + threadIdx.x] = (float)hist[threadIdx.x];
}

__device__ __forceinline__ unsigned int mix_hash(unsigned int h) {
    h ^= h >> 16; h *= 0x7feb352du;
    h ^= h >> 15; h *= 0x846ca68bu;
    h ^= h >> 16;
    return h;
}

__global__ __launch_bounds__(NTHREADS, 1)
void stats_mlp_kernel(const float* __restrict__ X,
                      const int*   __restrict__ y,
                      const float* __restrict__ w1,
                      const float* __restrict__ b1,
                      const float* __restrict__ w2,
                      const float* __restrict__ b2,
                      float* __restrict__ out) {
    extern __shared__ char smem[];
    unsigned int* tables = (unsigned int*)(smem + OFF_TABLES);
    int* ybuf = (int*)(smem + OFF_YBUF);

    const int tid = threadIdx.x;
    const int g  = blockIdx.x;       // feature group 0..127
    const int b  = blockIdx.y;       // batch 0..15
    const int f0 = g * COLS_PER_CTA;

    // init hash tables (32768 words) with EMPTY
    #pragma unroll
    for (int i = 0; i < (COLS_PER_CTA * TAB_SLOTS) / NTHREADS; i++)
        tables[tid + i * NTHREADS] = EMPTY_SLOT;
    // stage y for this batch
    #pragma unroll
    for (int i = 0; i < S_DIM / NTHREADS; i++)
        ybuf[tid + i * NTHREADS] = y[b * S_DIM + tid + i * NTHREADS];
    __syncthreads();

    const int col = tid & 3;         // 0..3 (keeps warp loads row-contiguous)
    const int r0  = tid >> 2;        // 0..127

    // per-thread accumulators (one column, 1/128 of the rows)
    float sum = 0.f, sumsq = 0.f, sumabs = 0.f, maxabs = 0.f, nanc = 0.f;
    float uniq = 0.f;
    float csum[NCLS];
    #pragma unroll
    for (int c = 0; c < NCLS; c++) csum[c] = 0.f;

    unsigned int* tab = tables + col * TAB_SLOTS;
    const float* Xb = X + ((size_t)b * S_DIM) * F_DIM + f0 + col;

    #pragma unroll 4
    for (int i = 0; i < S_DIM / 128; i++) {
        const int r = r0 + 128 * i;
        float x = Xb[(size_t)r * F_DIM];
        int yv = ybuf[r];
        bool isn = isnan(x);
        float v = isn ? 0.0f : x;
        nanc += isn ? 1.0f : 0.0f;
        sum += v;
        sumsq = fmaf(v, v, sumsq);
        float a = fabsf(v);
        sumabs += a;
        maxabs = fmaxf(maxabs, a);
        #pragma unroll
        for (int c = 0; c < NCLS; c++)
            csum[c] += (yv == c) ? v : 0.0f;

        // exact distinct count: bit-pattern equality after -0 canonicalization
        unsigned int bits = __float_as_uint(v == 0.0f ? 0.0f : v);
        unsigned int slot = mix_hash(bits) & (TAB_SLOTS - 1);
        while (true) {
            unsigned int cur = tab[slot];
            if (cur == bits) break;
            if (cur == EMPTY_SLOT) {
                unsigned int old = atomicCAS(&tab[slot], EMPTY_SLOT, bits);
                if (old == EMPTY_SLOT) { uniq += 1.0f; break; }
                if (old == bits) break;
            }
            slot = (slot + 1) & (TAB_SLOTS - 1);
        }
    }
    __syncthreads();   // everyone done with tables & ybuf

    // ---- deterministic tree reduction: 16 stats per thread ----
    float* buf = (float*)(smem + OFF_BUF);
    {
        float st[16] = {sum, sumsq, sumabs, maxabs, nanc, uniq,
                        csum[0], csum[1], csum[2], csum[3], csum[4],
                        csum[5], csum[6], csum[7], csum[8], csum[9]};
        #pragma unroll
        for (int s = 0; s < 16; s++) buf[tid * 17 + s] = st[s];
    }
    __syncthreads();
    #pragma unroll
    for (int off = 256; off >= 4; off >>= 1) {  // off multiple of 4 keeps col alignment
        if (tid < off) {
            #pragma unroll
            for (int s = 0; s < 16; s++) {
                float o = buf[(tid + off) * 17 + s];
                if (s == 3) buf[tid * 17 + s] = fmaxf(buf[tid * 17 + s], o);
                else        buf[tid * 17 + s] += o;
            }
        }
        __syncthreads();
    }

    // stage w2 into smem (region disjoint from buf)
    float* w2s = (float*)(smem + OFF_W2);
    #pragma unroll
    for (int i = 0; i < (HID * ODIM) / NTHREADS; i++)
        w2s[tid + i * NTHREADS] = w2[tid + i * NTHREADS];

    // ---- per-column final stats (threads 0..3) ----
    float* stats6 = (float*)(smem + OFF_STATS);
    if (tid < COLS_PER_CTA) {
        const float Sf = (float)S_DIM;
        float tsum    = buf[tid * 17 + 0];
        float tsumsq  = buf[tid * 17 + 1];
        float tsumabs = buf[tid * 17 + 2];
        float tmaxabs = buf[tid * 17 + 3];
        float tnan    = buf[tid * 17 + 4];
        float tuniq   = buf[tid * 17 + 5];
        float gmean = tsum / Sf;
        float var = fmaxf(tsumsq / Sf - gmean * gmean, 0.0f);
        float between = 0.0f;
        #pragma unroll
        for (int c = 0; c < NCLS; c++) {
            float cnt = g_class_counts[b * NCLS + c];
            float cm = buf[tid * 17 + 6 + c] / fmaxf(cnt, 1.0f);
            float d = cm - gmean;
            between = fmaf(cnt, d * d, between);
        }
        between /= Sf;
        float ts = between / fmaxf(var, 1e-6f);
        stats6[tid * 6 + 0] = ts;
        stats6[tid * 6 + 1] = tnan / Sf;
        stats6[tid * 6 + 2] = tuniq / Sf;
        stats6[tid * 6 + 3] = var;
        stats6[tid * 6 + 4] = tsumabs / Sf;
        stats6[tid * 6 + 5] = tmaxabs;
    }
    __syncthreads();

    // ---- MLP layer 1: h = gelu_exact(stats6 @ w1 + b1), 4 cols x 64 ----
    float* hsm = (float*)(smem + OFF_H);
    if (tid < COLS_PER_CTA * HID) {
        int ch = tid >> 6;       // column 0..3
        int j  = tid & 63;       // hidden unit
        float acc = b1[j];
        #pragma unroll
        for (int i = 0; i < 6; i++)
            acc = fmaf(stats6[ch * 6 + i], w1[i * HID + j], acc);
        float hv = 0.5f * acc * (1.0f + erff(acc * 0.70710678118654752f));
        hsm[ch * HID + j] = hv;
    }
    __syncthreads();

    // ---- MLP layer 2: out = h @ w2 + b2, 4 cols x 128 (one output/thread) ----
    {
        int ch = tid >> 7;       // column 0..3
        int k  = tid & 127;      // output unit
        float acc = b2[k];
        #pragma unroll
        for (int j = 0; j < HID; j++)
            acc = fmaf(hsm[ch * HID + j], w2s[j * ODIM + k], acc);
        out[(((size_t)b * F_DIM) + f0 + ch) * ODIM + k] = acc;
    }
}

extern "C" void kernel_launch(void* const* d_in, const int* in_sizes, int n_in,
                              void* d_out, int out_size) {
    const float* X  = (const float*)d_in[0];
    const int*   y  = (const int*)d_in[1];
    const float* w1 = (const float*)d_in[2];
    const float* b1 = (const float*)d_in[3];
    const float* w2 = (const float*)d_in[4];
    const float* b2 = (const float*)d_in[5];
    float* out = (float*)d_out;

    cudaFuncSetAttribute(stats_mlp_kernel,
                         cudaFuncAttributeMaxDynamicSharedMemorySize, SMEM_BYTES);

    class_count_kernel<<<B_DIM, 256>>>(y);
    dim3 grid(F_DIM / COLS_PER_CTA, B_DIM);
    stats_mlp_kernel<<<grid, NTHREADS, SMEM_BYTES>>>(X, y, w1, b1, w2, b2, out);
}